// round 3
// baseline (speedup 1.0000x reference)
#include <cuda_runtime.h>
#include <cuda_bf16.h>
#include <mma.h>

using namespace nvcuda;

// Problem constants
#define NTOK   8192
#define INDIM  4096
#define OUTDIM 4096
#define NE     8
#define RR     16
#define H4E    32
#define CAPACITY 3072          // int(3.0 * 8192 / 8)
#define ALPHA_ (1.0f/16.0f)
#define LN_EPS 1e-5f

// Scratch (no allocation allowed -> device globals)
__device__ float g_C2[NTOK * 128];      // augmented-A columns [N, E*R]
__device__ int   g_topi[NTOK * 2];
__device__ float g_topg[NTOK * 2];
__device__ int   g_counts[16];          // [k][e]

// ---------------------------------------------------------------------------
// cp.async helpers
// ---------------------------------------------------------------------------
__device__ __forceinline__ unsigned smem_u32(const void* p) {
    return (unsigned)__cvta_generic_to_shared(p);
}
__device__ __forceinline__ void cp16(void* dst, const void* src) {
    asm volatile("cp.async.cg.shared.global [%0], [%1], 16;\n"
                 :: "r"(smem_u32(dst)), "l"(src));
}
__device__ __forceinline__ void cp4(void* dst, const void* src) {
    asm volatile("cp.async.ca.shared.global [%0], [%1], 4;\n"
                 :: "r"(smem_u32(dst)), "l"(src));
}
__device__ __forceinline__ void cp_commit() {
    asm volatile("cp.async.commit_group;\n");
}
#define CP_WAIT(n) asm volatile("cp.async.wait_group %0;\n" :: "n"(n))

// ---------------------------------------------------------------------------
// Kernel 0: zero the routing counters
// ---------------------------------------------------------------------------
__global__ void zero_counts_kernel() {
    if (threadIdx.x < 16) g_counts[threadIdx.x] = 0;
}

// ---------------------------------------------------------------------------
// Kernel 1: gate = Linear(4096->32) -> LayerNorm -> ReLU -> Linear(32->8)
//           -> top-2 -> softmax over selected -> counts
// One block of 256 threads handles 64 tokens.
// ---------------------------------------------------------------------------
__global__ __launch_bounds__(256) void gate_kernel(
    const float* __restrict__ x,
    const float* __restrict__ gw1, const float* __restrict__ gb1,
    const float* __restrict__ gamma, const float* __restrict__ beta,
    const float* __restrict__ gw2, const float* __restrict__ gb2)
{
    __shared__ float Xs[64][65];   // [k][m]
    __shared__ float Wsh[64][33];  // [k][j]
    __shared__ float Hs[64][33];   // [m][j]

    const int tid = threadIdx.x;
    const int m0  = blockIdx.x * 64;
    const int mm  = tid & 63;
    const int jg  = tid >> 6;      // 0..3
    const int j0  = jg * 8;

    float acc[8];
#pragma unroll
    for (int jj = 0; jj < 8; jj++) acc[jj] = 0.f;

    for (int kc = 0; kc < 64; ++kc) {
        const int k0 = kc * 64;
        // load x chunk [64 tokens][64 k], store transposed [k][m]
#pragma unroll
        for (int i = 0; i < 4; i++) {
            int s  = tid + i * 256;        // 0..1023 float4 slots
            int m  = s >> 4;
            int f4 = (s & 15) * 4;
            float4 v = *(const float4*)(x + (size_t)(m0 + m) * INDIM + k0 + f4);
            Xs[f4 + 0][m] = v.x; Xs[f4 + 1][m] = v.y;
            Xs[f4 + 2][m] = v.z; Xs[f4 + 3][m] = v.w;
        }
        // load gw1 chunk [32 j][64 k], store transposed [k][j]
#pragma unroll
        for (int i = 0; i < 2; i++) {
            int s  = tid + i * 256;        // 0..511
            int j  = s >> 4;
            int f4 = (s & 15) * 4;
            float4 v = *(const float4*)(gw1 + (size_t)j * INDIM + k0 + f4);
            Wsh[f4 + 0][j] = v.x; Wsh[f4 + 1][j] = v.y;
            Wsh[f4 + 2][j] = v.z; Wsh[f4 + 3][j] = v.w;
        }
        __syncthreads();
#pragma unroll 16
        for (int kk = 0; kk < 64; ++kk) {
            float xv = Xs[kk][mm];
#pragma unroll
            for (int jj = 0; jj < 8; jj++) acc[jj] += xv * Wsh[kk][j0 + jj];
        }
        __syncthreads();
    }

#pragma unroll
    for (int jj = 0; jj < 8; jj++) Hs[mm][j0 + jj] = acc[jj];
    __syncthreads();

    if (tid < 64) {
        const int n = m0 + tid;
        float h[H4E];
        float mu = 0.f;
#pragma unroll
        for (int j = 0; j < H4E; j++) { h[j] = Hs[tid][j] + gb1[j]; mu += h[j]; }
        mu *= (1.0f / H4E);
        float var = 0.f;
#pragma unroll
        for (int j = 0; j < H4E; j++) { float d = h[j] - mu; var += d * d; }
        var *= (1.0f / H4E);
        const float inv = rsqrtf(var + LN_EPS);
#pragma unroll
        for (int j = 0; j < H4E; j++) {
            float v = (h[j] - mu) * inv * gamma[j] + beta[j];
            h[j] = fmaxf(v, 0.f);
        }
        // gates + top-2 (first-occurrence semantics, matching lax.top_k ties)
        float best = -3.4e38f, second = -3.4e38f;
        int be = 0, se = 0;
#pragma unroll
        for (int e = 0; e < NE; e++) {
            float g = gb2[e];
#pragma unroll
            for (int j = 0; j < H4E; j++) g += h[j] * gw2[e * H4E + j];
            if (g > best)      { second = best; se = be; best = g; be = e; }
            else if (g > second) { second = g; se = e; }
        }
        const float e1 = __expf(second - best);
        const float s  = 1.f + e1;
        g_topi[n * 2 + 0] = be;
        g_topi[n * 2 + 1] = se;
        g_topg[n * 2 + 0] = 1.f / s;
        g_topg[n * 2 + 1] = e1 / s;
        atomicAdd(&g_counts[be], 1);
        atomicAdd(&g_counts[8 + se], 1);
    }
}

// ---------------------------------------------------------------------------
// Kernel 2: C2[n, e*16+r] = w[n,e] * ALPHA * dot(x[n], lora_A[e][:, r])
// One block (128 threads) per token. r4 = (tid&3)*4 (4 r's per thread),
// p = tid>>2 (32 K-stripes of 128).
// ---------------------------------------------------------------------------
__global__ __launch_bounds__(128) void coeff_kernel(
    const float* __restrict__ x, const float* __restrict__ lA)
{
    const int n   = blockIdx.x;
    const int tid = threadIdx.x;

    g_C2[(size_t)n * 128 + tid] = 0.f;   // zero full row first

    const int   e0 = g_topi[n * 2 + 0];
    const int   e1 = g_topi[n * 2 + 1];
    const float w0 = g_topg[n * 2 + 0] * (g_counts[e0]     <= CAPACITY ? 1.f : 0.f);
    const float w1 = g_topg[n * 2 + 1] * (g_counts[8 + e1] <= CAPACITY ? 1.f : 0.f);

    const int r4 = (tid & 3) << 2;
    const int p  = tid >> 2;
    const int i0 = p * 128;

    const float* xr  = x  + (size_t)n  * INDIM;
    const float* A0b = lA + (size_t)e0 * INDIM * RR;
    const float* A1b = lA + (size_t)e1 * INDIM * RR;

    float acc0[4] = {0.f, 0.f, 0.f, 0.f};
    float acc1[4] = {0.f, 0.f, 0.f, 0.f};

    for (int ii = 0; ii < 128; ii += 4) {
        float4 xv = *(const float4*)(xr + i0 + ii);
        float xs[4] = {xv.x, xv.y, xv.z, xv.w};
#pragma unroll
        for (int q = 0; q < 4; q++) {
            const int i = i0 + ii + q;
            float4 a0 = *(const float4*)(A0b + (size_t)i * RR + r4);
            float4 a1 = *(const float4*)(A1b + (size_t)i * RR + r4);
            acc0[0] += xs[q] * a0.x; acc0[1] += xs[q] * a0.y;
            acc0[2] += xs[q] * a0.z; acc0[3] += xs[q] * a0.w;
            acc1[0] += xs[q] * a1.x; acc1[1] += xs[q] * a1.y;
            acc1[2] += xs[q] * a1.z; acc1[3] += xs[q] * a1.w;
        }
    }

    __shared__ float sh[2][32 * 16];
#pragma unroll
    for (int j = 0; j < 4; j++) {
        sh[0][p * 16 + r4 + j] = acc0[j];
        sh[1][p * 16 + r4 + j] = acc1[j];
    }
    __syncthreads();
    for (int off = 16; off >= 1; off >>= 1) {
        for (int s2 = tid; s2 < off * 16; s2 += 128) {
            const int pp = s2 >> 4, r = s2 & 15;
            sh[0][pp * 16 + r] += sh[0][(pp + off) * 16 + r];
            sh[1][pp * 16 + r] += sh[1][(pp + off) * 16 + r];
        }
        __syncthreads();
    }
    if (tid < 16) {
        g_C2[(size_t)n * 128 + e0 * 16 + tid] = w0 * ALPHA_ * sh[0][tid];
        g_C2[(size_t)n * 128 + e1 * 16 + tid] = w1 * ALPHA_ * sh[1][tid];
    }
}

// ---------------------------------------------------------------------------
// Kernel 3: augmented-K TF32 GEMM.
// out[n,o] = sum_{k<4096} x[n,k] W[o,k]  +  sum_{j<128} C2[n,j] loraB_flat[j,o]
// BM=BN=128, BK=16, 256 threads (8 warps: 4 in M x 2 in N), warp tile 32x64,
// wmma m16n16k8 TF32, 2-stage cp.async double buffering.
// ---------------------------------------------------------------------------
#define BM 128
#define BN 128
#define BK 16
#define ALD 24
#define BLD 24
#define ASZ (BM * ALD)
#define BSZ (BN * BLD)
#define KTILES 264   // (4096 + 128) / 16

__global__ __launch_bounds__(256) void main_gemm_kernel(
    const float* __restrict__ x, const float* __restrict__ W,
    const float* __restrict__ LB, float* __restrict__ out)
{
    extern __shared__ float smem[];
    float* Asm = smem;              // [2][ASZ]
    float* Bsm = smem + 2 * ASZ;    // [2][BSZ]

    const int tid = threadIdx.x;
    const int gm0 = blockIdx.y * BM;
    const int gn0 = blockIdx.x * BN;
    const int warp = tid >> 5;
    const int wm = warp & 3;        // 0..3 -> M offset wm*32
    const int wn = warp >> 2;       // 0..1 -> N offset wn*64

    wmma::fragment<wmma::accumulator, 16, 16, 8, float> cf[2][4];
#pragma unroll
    for (int i = 0; i < 2; i++)
#pragma unroll
        for (int j = 0; j < 4; j++) wmma::fill_fragment(cf[i][j], 0.f);

    auto load_tile = [&](int kt, int buf) {
        float* Ad = Asm + buf * ASZ;
        float* Bd = Bsm + buf * BSZ;
        const int k0 = kt * BK;
        // ---- A tile ----
        const float* Abase;
        int Ald_;
        if (k0 < INDIM) { Abase = x + (size_t)gm0 * INDIM + k0;         Ald_ = INDIM; }
        else            { Abase = g_C2 + (size_t)gm0 * 128 + (k0 - INDIM); Ald_ = 128; }
#pragma unroll
        for (int i = 0; i < 2; i++) {
            int s  = tid + i * 256;       // 0..511 float4 slots
            int m  = s >> 2;
            int f4 = (s & 3) << 2;
            cp16(Ad + m * ALD + f4, Abase + (size_t)m * Ald_ + f4);
        }
        // ---- B tile (col-major [n][k]) ----
        if (k0 < INDIM) {
            const float* Bbase = W + (size_t)gn0 * INDIM + k0;
#pragma unroll
            for (int i = 0; i < 2; i++) {
                int s  = tid + i * 256;
                int nn = s >> 2;
                int f4 = (s & 3) << 2;
                cp16(Bd + nn * BLD + f4, Bbase + (size_t)nn * INDIM + f4);
            }
        } else {
            // loraB_flat[j, o] is row-major in o -> scalar cp.async, coalesced in o
            const float* Lbase = LB + (size_t)(k0 - INDIM) * OUTDIM + gn0;
#pragma unroll
            for (int i = 0; i < 8; i++) {
                int s  = tid + (i << 8);   // 0..2047
                int k  = s >> 7;
                int nn = s & 127;
                cp4(Bd + nn * BLD + k, Lbase + (size_t)k * OUTDIM + nn);
            }
        }
        cp_commit();
    };

    load_tile(0, 0);
    for (int kt = 0; kt < KTILES; ++kt) {
        const int buf = kt & 1;
        if (kt + 1 < KTILES) { load_tile(kt + 1, buf ^ 1); CP_WAIT(1); }
        else                 { CP_WAIT(0); }
        __syncthreads();

        const float* Ad = Asm + buf * ASZ;
        const float* Bd = Bsm + buf * BSZ;
#pragma unroll
        for (int kk = 0; kk < BK; kk += 8) {
            wmma::fragment<wmma::matrix_a, 16, 16, 8, wmma::precision::tf32, wmma::row_major> af[2];
            wmma::fragment<wmma::matrix_b, 16, 16, 8, wmma::precision::tf32, wmma::col_major> bf[4];
#pragma unroll
            for (int i = 0; i < 2; i++) {
                wmma::load_matrix_sync(af[i], Ad + (wm * 32 + i * 16) * ALD + kk, ALD);
#pragma unroll
                for (int t = 0; t < af[i].num_elements; t++)
                    af[i].x[t] = wmma::__float_to_tf32(af[i].x[t]);
            }
#pragma unroll
            for (int j = 0; j < 4; j++) {
                wmma::load_matrix_sync(bf[j], Bd + (wn * 64 + j * 16) * BLD + kk, BLD);
#pragma unroll
                for (int t = 0; t < bf[j].num_elements; t++)
                    bf[j].x[t] = wmma::__float_to_tf32(bf[j].x[t]);
            }
#pragma unroll
            for (int i = 0; i < 2; i++)
#pragma unroll
                for (int j = 0; j < 4; j++)
                    wmma::mma_sync(cf[i][j], af[i], bf[j], cf[i][j]);
        }
        __syncthreads();
    }

#pragma unroll
    for (int i = 0; i < 2; i++)
#pragma unroll
        for (int j = 0; j < 4; j++)
            wmma::store_matrix_sync(
                out + (size_t)(gm0 + wm * 32 + i * 16) * OUTDIM + gn0 + wn * 64 + j * 16,
                cf[i][j], OUTDIM, wmma::mem_row_major);
}

// ---------------------------------------------------------------------------
// Host entry
// ---------------------------------------------------------------------------
extern "C" void kernel_launch(void* const* d_in, const int* in_sizes, int n_in,
                              void* d_out, int out_size)
{
    const float* x    = (const float*)d_in[0];
    const float* W    = (const float*)d_in[1];
    const float* lA   = (const float*)d_in[2];
    const float* lB   = (const float*)d_in[3];
    const float* gw1  = (const float*)d_in[4];
    const float* gb1  = (const float*)d_in[5];
    const float* gam  = (const float*)d_in[6];
    const float* bet  = (const float*)d_in[7];
    const float* gw2  = (const float*)d_in[8];
    const float* gb2  = (const float*)d_in[9];
    float* out = (float*)d_out;

    zero_counts_kernel<<<1, 32>>>();
    gate_kernel<<<NTOK / 64, 256>>>(x, gw1, gb1, gam, bet, gw2, gb2);
    coeff_kernel<<<NTOK, 128>>>(x, lA);

    const size_t smem_bytes = 2 * (ASZ + BSZ) * sizeof(float);  // 49152
    main_gemm_kernel<<<dim3(OUTDIM / BN, NTOK / BM), 256, smem_bytes>>>(x, W, lB, out);
}

// round 7
// speedup vs baseline: 1.7046x; 1.7046x over previous
#include <cuda_runtime.h>
#include <cuda_fp16.h>
#include <cstdint>

// ---------------------------------------------------------------------------
// Problem constants
// ---------------------------------------------------------------------------
#define NTOK   8192
#define INDIM  4096
#define OUTDIM 4096
#define NE     8
#define RR     16
#define H4E    32
#define CAPACITY 3072          // int(3.0 * 8192 / 8)
#define ALPHA_ (1.0f/16.0f)
#define LN_EPS 1e-5f

// Augmented-K GEMM: kts 0..3 = lora columns (fp16 direct), 4..131 = fp32 main
#define KT     132
#define LORA_KT 4
#define LDF    36              // fp32 smem row pad (floats) - conflict-free
#define LDT    40              // fp16 smem row pad (halves) - conflict-free ldmatrix
#define SF     (2 * 128 * LDF * 4)   // fp32 stage bytes (A+B) = 36864
#define SH     (2 * 128 * LDT * 2)   // fp16 stage bytes (A+B) = 20480
#define FOFF   0
#define HOFF   (3 * SF)              // 110592
#define GEMM_SMEM (3 * SF + 3 * SH)  // 172032

// ---------------------------------------------------------------------------
// Device scratch (small! ~4.2 MB total; large globals trip the mem guard)
// ---------------------------------------------------------------------------
__device__ __align__(1024) __half g_C2[NTOK * 128];     // gated lora coeffs (fp16)
__device__ __align__(1024) __half g_LBT[OUTDIM * 128];  // lora_B^T [o][j] (fp16)
__device__ int   g_topi[NTOK * 2];
__device__ float g_topg[NTOK * 2];
__device__ int   g_counts[16];          // [k][e]
__device__ int   g_ecount[NE];
__device__ int   g_elist[NE * 16384];
__device__ float g_ew[NE * 16384];

// ---------------------------------------------------------------------------
// PTX helpers
// ---------------------------------------------------------------------------
__device__ __forceinline__ uint32_t smem_u32(const void* p) {
    return (uint32_t)__cvta_generic_to_shared(p);
}
__device__ __forceinline__ void cp16(void* dst, const void* src) {
    asm volatile("cp.async.cg.shared.global [%0], [%1], 16;\n"
                 :: "r"(smem_u32(dst)), "l"(src));
}
__device__ __forceinline__ void cp_commit() {
    asm volatile("cp.async.commit_group;\n");
}
#define CP_WAIT(n) asm volatile("cp.async.wait_group %0;\n" :: "n"(n))

__device__ __forceinline__ void ldsm4(uint32_t& r0, uint32_t& r1,
                                      uint32_t& r2, uint32_t& r3, uint32_t addr) {
    asm volatile("ldmatrix.sync.aligned.m8n8.x4.shared.b16 {%0,%1,%2,%3}, [%4];"
                 : "=r"(r0), "=r"(r1), "=r"(r2), "=r"(r3) : "r"(addr));
}
__device__ __forceinline__ void mma16816(float* c, const uint32_t* a, const uint32_t* b) {
    asm volatile(
        "mma.sync.aligned.m16n8k16.row.col.f32.f16.f16.f32 "
        "{%0,%1,%2,%3}, {%4,%5,%6,%7}, {%8,%9}, {%0,%1,%2,%3};"
        : "+f"(c[0]), "+f"(c[1]), "+f"(c[2]), "+f"(c[3])
        : "r"(a[0]), "r"(a[1]), "r"(a[2]), "r"(a[3]), "r"(b[0]), "r"(b[1]));
}

// ---------------------------------------------------------------------------
// Kernel: zero counters
// ---------------------------------------------------------------------------
__global__ void zero_kernel() {
    int t = threadIdx.x;
    if (t < 16) g_counts[t] = 0;
    if (t < NE) g_ecount[t] = 0;
}

// ---------------------------------------------------------------------------
// Kernel: lora_B transpose: g_LBT[o][j] = half(LB[j][o])
// ---------------------------------------------------------------------------
__global__ __launch_bounds__(256) void lbt_kernel(const float* __restrict__ LB)
{
    const int o = blockIdx.x * 256 + threadIdx.x;
    const int j = blockIdx.y;
    g_LBT[(size_t)o * 128 + j] = __float2half_rn(LB[(size_t)j * OUTDIM + o]);
}

// ---------------------------------------------------------------------------
// Kernel: gate = Linear(4096->32) -> LN -> ReLU -> Linear(32->8) -> top2
// (verified: produced rel_err 2.94e-4 end-to-end in R2/R3)
// ---------------------------------------------------------------------------
__global__ __launch_bounds__(256) void gate_kernel(
    const float* __restrict__ x,
    const float* __restrict__ gw1, const float* __restrict__ gb1,
    const float* __restrict__ gamma, const float* __restrict__ beta,
    const float* __restrict__ gw2, const float* __restrict__ gb2)
{
    __shared__ float Xs[64][65];
    __shared__ float Wsh[64][33];
    __shared__ float Hs[64][33];

    const int tid = threadIdx.x;
    const int m0  = blockIdx.x * 64;
    const int mm  = tid & 63;
    const int jg  = tid >> 6;
    const int j0  = jg * 8;

    float acc[8];
#pragma unroll
    for (int jj = 0; jj < 8; jj++) acc[jj] = 0.f;

    for (int kc = 0; kc < 64; ++kc) {
        const int k0 = kc * 64;
#pragma unroll
        for (int i = 0; i < 4; i++) {
            int s  = tid + i * 256;
            int m  = s >> 4;
            int f4 = (s & 15) * 4;
            float4 v = *(const float4*)(x + (size_t)(m0 + m) * INDIM + k0 + f4);
            Xs[f4 + 0][m] = v.x; Xs[f4 + 1][m] = v.y;
            Xs[f4 + 2][m] = v.z; Xs[f4 + 3][m] = v.w;
        }
#pragma unroll
        for (int i = 0; i < 2; i++) {
            int s  = tid + i * 256;
            int j  = s >> 4;
            int f4 = (s & 15) * 4;
            float4 v = *(const float4*)(gw1 + (size_t)j * INDIM + k0 + f4);
            Wsh[f4 + 0][j] = v.x; Wsh[f4 + 1][j] = v.y;
            Wsh[f4 + 2][j] = v.z; Wsh[f4 + 3][j] = v.w;
        }
        __syncthreads();
#pragma unroll 16
        for (int kk = 0; kk < 64; ++kk) {
            float xv = Xs[kk][mm];
#pragma unroll
            for (int jj = 0; jj < 8; jj++) acc[jj] += xv * Wsh[kk][j0 + jj];
        }
        __syncthreads();
    }

#pragma unroll
    for (int jj = 0; jj < 8; jj++) Hs[mm][j0 + jj] = acc[jj];
    __syncthreads();

    if (tid < 64) {
        const int n = m0 + tid;
        float h[H4E];
        float mu = 0.f;
#pragma unroll
        for (int j = 0; j < H4E; j++) { h[j] = Hs[tid][j] + gb1[j]; mu += h[j]; }
        mu *= (1.0f / H4E);
        float var = 0.f;
#pragma unroll
        for (int j = 0; j < H4E; j++) { float d = h[j] - mu; var += d * d; }
        var *= (1.0f / H4E);
        const float inv = rsqrtf(var + LN_EPS);
#pragma unroll
        for (int j = 0; j < H4E; j++) {
            float v = (h[j] - mu) * inv * gamma[j] + beta[j];
            h[j] = fmaxf(v, 0.f);
        }
        float best = -3.4e38f, second = -3.4e38f;
        int be = 0, se = 0;
#pragma unroll
        for (int e = 0; e < NE; e++) {
            float g = gb2[e];
#pragma unroll
            for (int j = 0; j < H4E; j++) g += h[j] * gw2[e * H4E + j];
            if (g > best)        { second = best; se = be; best = g; be = e; }
            else if (g > second) { second = g; se = e; }
        }
        const float e1 = __expf(second - best);
        const float s  = 1.f + e1;
        g_topi[n * 2 + 0] = be;
        g_topi[n * 2 + 1] = se;
        g_topg[n * 2 + 0] = 1.f / s;
        g_topg[n * 2 + 1] = e1 / s;
        atomicAdd(&g_counts[be], 1);
        atomicAdd(&g_counts[8 + se], 1);
    }
}

// ---------------------------------------------------------------------------
// Kernel: route tokens into per-expert lists (capacity-filtered, ALPHA folded)
// ---------------------------------------------------------------------------
__global__ __launch_bounds__(256) void route_kernel()
{
    int n = blockIdx.x * 256 + threadIdx.x;
    if (n >= NTOK) return;
#pragma unroll
    for (int k = 0; k < 2; k++) {
        int e   = g_topi[n * 2 + k];
        float w = g_topg[n * 2 + k];
        if (g_counts[k * 8 + e] > CAPACITY) w = 0.f;
        if (w != 0.f) {
            int idx = atomicAdd(&g_ecount[e], 1);
            g_elist[e * 16384 + idx] = n;
            g_ew[e * 16384 + idx]    = w * ALPHA_;
        }
    }
}

// ---------------------------------------------------------------------------
// Kernel: expert-gathered coeff -> fp16 into g_C2 columns:
// g_C2[n][e*16+r] = half( w_n * alpha * sum_i x[n,i] A[e,i,r] )
// ---------------------------------------------------------------------------
__global__ __launch_bounds__(128) void coeff2_kernel(
    const float* __restrict__ x, const float* __restrict__ lA)
{
    __shared__ float Xs[128][33];
    __shared__ float As[32][16];
    __shared__ int   Ts[128];
    __shared__ float Wsc[128];

    const int e    = blockIdx.x;
    const int base = blockIdx.y * 128;
    const int cnt  = g_ecount[e];
    if (base >= cnt) return;
    const int tid = threadIdx.x;
    const int T   = min(128, cnt - base);

    {
        int i = min(tid, T - 1);
        Ts[tid]  = g_elist[e * 16384 + base + i];
        Wsc[tid] = g_ew[e * 16384 + base + i];
    }
    __syncthreads();

    float acc[16];
#pragma unroll
    for (int r = 0; r < 16; r++) acc[r] = 0.f;

    const float* Ae = lA + (size_t)e * INDIM * RR;

    for (int k0 = 0; k0 < INDIM; k0 += 32) {
#pragma unroll
        for (int i = 0; i < 8; i++) {
            int s   = tid + i * 128;
            int row = s >> 3;
            int f4  = (s & 7) << 2;
            float4 v = *(const float4*)(x + (size_t)Ts[row] * INDIM + k0 + f4);
            Xs[row][f4 + 0] = v.x; Xs[row][f4 + 1] = v.y;
            Xs[row][f4 + 2] = v.z; Xs[row][f4 + 3] = v.w;
        }
#pragma unroll
        for (int i = 0; i < 4; i++) {
            int s  = tid + i * 128;
            int kk = s >> 4;
            int r  = s & 15;
            As[kk][r] = Ae[(size_t)(k0 + kk) * RR + r];
        }
        __syncthreads();
#pragma unroll 8
        for (int kk = 0; kk < 32; kk++) {
            float xv = Xs[tid][kk];
            float4 a0 = *(const float4*)&As[kk][0];
            float4 a1 = *(const float4*)&As[kk][4];
            float4 a2 = *(const float4*)&As[kk][8];
            float4 a3 = *(const float4*)&As[kk][12];
            acc[0]  += xv * a0.x; acc[1]  += xv * a0.y; acc[2]  += xv * a0.z; acc[3]  += xv * a0.w;
            acc[4]  += xv * a1.x; acc[5]  += xv * a1.y; acc[6]  += xv * a1.z; acc[7]  += xv * a1.w;
            acc[8]  += xv * a2.x; acc[9]  += xv * a2.y; acc[10] += xv * a2.z; acc[11] += xv * a2.w;
            acc[12] += xv * a3.x; acc[13] += xv * a3.y; acc[14] += xv * a3.z; acc[15] += xv * a3.w;
        }
        __syncthreads();
    }

    if (tid < T) {
        float w = Wsc[tid];
        __half* dst = g_C2 + (size_t)Ts[tid] * 128 + e * RR;
#pragma unroll
        for (int r = 0; r < 16; r++) dst[r] = __float2half_rn(w * acc[r]);
    }
}

// ---------------------------------------------------------------------------
// Kernel: fp16 mma.sync GEMM, augmented K. fp32 x/W streamed via cp.async and
// converted fp32->fp16 in smem; lora columns (fp16) loaded directly as kts 0..3.
// BM=BN=128, 256 threads (8 warps 4x2), warp tile 32x64, 3-stage pipeline.
// ---------------------------------------------------------------------------
__global__ __launch_bounds__(256) void gemm_kernel(
    const float* __restrict__ x, const float* __restrict__ W,
    float* __restrict__ out)
{
    extern __shared__ uint8_t smem[];

    const int tid  = threadIdx.x;
    const int lane = tid & 31;
    const int warp = tid >> 5;
    const int wm   = warp & 3;
    const int wn   = warp >> 2;

    // panel swizzle: 4 panels of 16 m-blocks x 32 n-blocks
    const int b     = blockIdx.x;
    const int panel = b >> 9;
    const int r     = b & 511;
    const int m0    = (panel * 16 + (r & 15)) * 128;
    const int n0    = (r >> 4) * 128;

    float acc[2][8][4];
#pragma unroll
    for (int i = 0; i < 2; i++)
#pragma unroll
        for (int j = 0; j < 8; j++)
#pragma unroll
            for (int q = 0; q < 4; q++) acc[i][j][q] = 0.f;

    auto fbuf = [&](int s) -> float* { return (float*)(smem + FOFF + s * SF); };
    auto hbuf = [&](int s) -> __half* { return (__half*)(smem + HOFF + s * SH); };

    auto load_stage = [&](int kt, int s) {
        if (kt < LORA_KT) {
            __half* Ah = hbuf(s);
            __half* Bh = Ah + 128 * LDT;
            const int jb = kt * 32;
#pragma unroll
            for (int i = 0; i < 2; i++) {
                int s2  = tid + i * 256;
                int row = s2 >> 2;
                int c   = (s2 & 3) * 8;
                cp16(Ah + row * LDT + c, g_C2 + (size_t)(m0 + row) * 128 + jb + c);
                cp16(Bh + row * LDT + c, g_LBT + (size_t)(n0 + row) * 128 + jb + c);
            }
        } else {
            float* Af = fbuf(s);
            float* Bf = Af + 128 * LDF;
            const int k0 = (kt - LORA_KT) * 32;
#pragma unroll
            for (int i = 0; i < 4; i++) {
                int s2  = tid + i * 256;
                int row = s2 >> 3;
                int c   = (s2 & 7) * 4;
                cp16(Af + row * LDF + c, x + (size_t)(m0 + row) * INDIM + k0 + c);
                cp16(Bf + row * LDF + c, W + (size_t)(n0 + row) * INDIM + k0 + c);
            }
        }
    };

    auto convert = [&](int s) {
        const int row = tid & 127;
        const int ch  = (tid >> 7) * 16;
#pragma unroll
        for (int t2 = 0; t2 < 2; t2++) {
            const float* src = fbuf(s) + t2 * 128 * LDF + row * LDF + ch;
            __half* dst = hbuf(s) + t2 * 128 * LDT + row * LDT + ch;
            float4 v0 = *(const float4*)(src + 0);
            float4 v1 = *(const float4*)(src + 4);
            float4 v2 = *(const float4*)(src + 8);
            float4 v3 = *(const float4*)(src + 12);
            __half2 h[8];
            h[0] = __floats2half2_rn(v0.x, v0.y); h[1] = __floats2half2_rn(v0.z, v0.w);
            h[2] = __floats2half2_rn(v1.x, v1.y); h[3] = __floats2half2_rn(v1.z, v1.w);
            h[4] = __floats2half2_rn(v2.x, v2.y); h[5] = __floats2half2_rn(v2.z, v2.w);
            h[6] = __floats2half2_rn(v3.x, v3.y); h[7] = __floats2half2_rn(v3.z, v3.w);
            *(uint4*)(dst + 0) = *(uint4*)&h[0];
            *(uint4*)(dst + 8) = *(uint4*)&h[4];
        }
    };

    load_stage(0, 0); cp_commit();
    load_stage(1, 1); cp_commit();

    for (int kt = 0; kt < KT; kt++) {
        CP_WAIT(1);
        __syncthreads();
        if (kt + 2 < KT) load_stage(kt + 2, (kt + 2) % 3);
        cp_commit();

        const int s = kt % 3;
        if (kt >= LORA_KT) convert(s);
        __syncthreads();

        const uint32_t ab = smem_u32(hbuf(s));
        const uint32_t bb = ab + 128 * LDT * 2;
#pragma unroll
        for (int step = 0; step < 2; step++) {
            const uint32_t abase = ab +
                ((wm * 32 + (lane & 15)) * LDT + step * 16 + (lane >> 4) * 8) * 2;
            const uint32_t bbase = bb +
                ((wn * 64 + (lane & 15)) * LDT + step * 16 + (lane >> 4) * 8) * 2;
            uint32_t A[2][4];
            uint32_t Bf[8][2];
#pragma unroll
            for (int i = 0; i < 2; i++)
                ldsm4(A[i][0], A[i][1], A[i][2], A[i][3], abase + i * 16 * LDT * 2);
#pragma unroll
            for (int j = 0; j < 4; j++) {
                uint32_t r0, r1, r2, r3;
                ldsm4(r0, r1, r2, r3, bbase + j * 16 * LDT * 2);
                Bf[2 * j][0] = r0; Bf[2 * j][1] = r2;
                Bf[2 * j + 1][0] = r1; Bf[2 * j + 1][1] = r3;
            }
#pragma unroll
            for (int i = 0; i < 2; i++)
#pragma unroll
                for (int j = 0; j < 8; j++)
                    mma16816(acc[i][j], A[i], Bf[j]);
        }
    }

    // epilogue
#pragma unroll
    for (int i = 0; i < 2; i++) {
        const int mrow = m0 + wm * 32 + i * 16 + (lane >> 2);
#pragma unroll
        for (int j = 0; j < 8; j++) {
            const int col = n0 + wn * 64 + j * 8 + (lane & 3) * 2;
            float2 v0 = make_float2(acc[i][j][0], acc[i][j][1]);
            float2 v1 = make_float2(acc[i][j][2], acc[i][j][3]);
            *(float2*)(out + (size_t)mrow * OUTDIM + col)       = v0;
            *(float2*)(out + (size_t)(mrow + 8) * OUTDIM + col) = v1;
        }
    }
}

// ---------------------------------------------------------------------------
// Host entry
// ---------------------------------------------------------------------------
extern "C" void kernel_launch(void* const* d_in, const int* in_sizes, int n_in,
                              void* d_out, int out_size)
{
    const float* x   = (const float*)d_in[0];
    const float* W   = (const float*)d_in[1];
    const float* lA  = (const float*)d_in[2];
    const float* lB  = (const float*)d_in[3];
    const float* gw1 = (const float*)d_in[4];
    const float* gb1 = (const float*)d_in[5];
    const float* gam = (const float*)d_in[6];
    const float* bet = (const float*)d_in[7];
    const float* gw2 = (const float*)d_in[8];
    const float* gb2 = (const float*)d_in[9];
    float* out = (float*)d_out;

    void* p_c2 = nullptr;
    cudaGetSymbolAddress(&p_c2, g_C2);

    zero_kernel<<<1, 32>>>();
    cudaMemsetAsync(p_c2, 0, (size_t)NTOK * 128 * sizeof(__half), 0);
    lbt_kernel<<<dim3(OUTDIM / 256, 128), 256>>>(lB);

    gate_kernel<<<NTOK / 64, 256>>>(x, gw1, gb1, gam, bet, gw2, gb2);
    route_kernel<<<NTOK / 256, 256>>>();
    coeff2_kernel<<<dim3(NE, 128), 128>>>(x, lA);

    cudaFuncSetAttribute(gemm_kernel, cudaFuncAttributeMaxDynamicSharedMemorySize,
                         GEMM_SMEM);
    gemm_kernel<<<2048, 256, GEMM_SMEM>>>(x, W, out);
}

// round 8
// speedup vs baseline: 2.2467x; 1.3180x over previous
#include <cuda_runtime.h>
#include <cuda_fp16.h>
#include <cstdint>

// ---------------------------------------------------------------------------
// Problem constants
// ---------------------------------------------------------------------------
#define NTOK   8192
#define INDIM  4096
#define OUTDIM 4096
#define NE     8
#define RR     16
#define H4E    32
#define CAPACITY 3072          // int(3.0 * 8192 / 8)
#define ALPHA_ (1.0f/16.0f)
#define LN_EPS 1e-5f

// Augmented-K GEMM: kts 0..3 = lora columns (fp16 direct), 4..131 = fp32 main
#define KT      132
#define LORA_KT 4
#define LDT     40             // fp16 smem row pad (halves): conflict-free ldmatrix
#define STAGEH  (2 * 128 * LDT)  // halves per stage (A+B) = 10240

// ---------------------------------------------------------------------------
// Device scratch (~4.2 MB total; large globals trip the mem guard)
// ---------------------------------------------------------------------------
__device__ __align__(1024) __half g_C2[NTOK * 128];     // gated lora coeffs (fp16)
__device__ __align__(1024) __half g_LBT[OUTDIM * 128];  // lora_B^T [o][j] (fp16)
__device__ int   g_topi[NTOK * 2];
__device__ float g_topg[NTOK * 2];
__device__ int   g_counts[16];          // [k][e]
__device__ int   g_ecount[NE];
__device__ int   g_elist[NE * 16384];
__device__ float g_ew[NE * 16384];

// ---------------------------------------------------------------------------
// PTX helpers
// ---------------------------------------------------------------------------
__device__ __forceinline__ uint32_t smem_u32(const void* p) {
    return (uint32_t)__cvta_generic_to_shared(p);
}
__device__ __forceinline__ void ldsm4(uint32_t& r0, uint32_t& r1,
                                      uint32_t& r2, uint32_t& r3, uint32_t addr) {
    asm volatile("ldmatrix.sync.aligned.m8n8.x4.shared.b16 {%0,%1,%2,%3}, [%4];"
                 : "=r"(r0), "=r"(r1), "=r"(r2), "=r"(r3) : "r"(addr));
}
__device__ __forceinline__ void mma16816(float* c, const uint32_t* a, const uint32_t* b) {
    asm volatile(
        "mma.sync.aligned.m16n8k16.row.col.f32.f16.f16.f32 "
        "{%0,%1,%2,%3}, {%4,%5,%6,%7}, {%8,%9}, {%0,%1,%2,%3};"
        : "+f"(c[0]), "+f"(c[1]), "+f"(c[2]), "+f"(c[3])
        : "r"(a[0]), "r"(a[1]), "r"(a[2]), "r"(a[3]), "r"(b[0]), "r"(b[1]));
}
__device__ __forceinline__ uint32_t packh2(float a, float b) {
    __half2 h = __floats2half2_rn(a, b);
    return *(uint32_t*)&h;
}

// ---------------------------------------------------------------------------
// Kernel: zero counters
// ---------------------------------------------------------------------------
__global__ void zero_kernel() {
    int t = threadIdx.x;
    if (t < 16) g_counts[t] = 0;
    if (t < NE) g_ecount[t] = 0;
}

// ---------------------------------------------------------------------------
// Kernel: lora_B transpose: g_LBT[o][j] = half(LB[j][o])
// ---------------------------------------------------------------------------
__global__ __launch_bounds__(256) void lbt_kernel(const float* __restrict__ LB)
{
    const int o = blockIdx.x * 256 + threadIdx.x;
    const int j = blockIdx.y;
    g_LBT[(size_t)o * 128 + j] = __float2half_rn(LB[(size_t)j * OUTDIM + o]);
}

// ---------------------------------------------------------------------------
// Kernel: gate = Linear(4096->32) -> LN -> ReLU -> Linear(32->8) -> top2
// (verified: rel_err 2.9e-4 end-to-end since R2)
// ---------------------------------------------------------------------------
__global__ __launch_bounds__(256) void gate_kernel(
    const float* __restrict__ x,
    const float* __restrict__ gw1, const float* __restrict__ gb1,
    const float* __restrict__ gamma, const float* __restrict__ beta,
    const float* __restrict__ gw2, const float* __restrict__ gb2)
{
    __shared__ float Xs[64][65];
    __shared__ float Wsh[64][33];
    __shared__ float Hs[64][33];

    const int tid = threadIdx.x;
    const int m0  = blockIdx.x * 64;
    const int mm  = tid & 63;
    const int jg  = tid >> 6;
    const int j0  = jg * 8;

    float acc[8];
#pragma unroll
    for (int jj = 0; jj < 8; jj++) acc[jj] = 0.f;

    for (int kc = 0; kc < 64; ++kc) {
        const int k0 = kc * 64;
#pragma unroll
        for (int i = 0; i < 4; i++) {
            int s  = tid + i * 256;
            int m  = s >> 4;
            int f4 = (s & 15) * 4;
            float4 v = *(const float4*)(x + (size_t)(m0 + m) * INDIM + k0 + f4);
            Xs[f4 + 0][m] = v.x; Xs[f4 + 1][m] = v.y;
            Xs[f4 + 2][m] = v.z; Xs[f4 + 3][m] = v.w;
        }
#pragma unroll
        for (int i = 0; i < 2; i++) {
            int s  = tid + i * 256;
            int j  = s >> 4;
            int f4 = (s & 15) * 4;
            float4 v = *(const float4*)(gw1 + (size_t)j * INDIM + k0 + f4);
            Wsh[f4 + 0][j] = v.x; Wsh[f4 + 1][j] = v.y;
            Wsh[f4 + 2][j] = v.z; Wsh[f4 + 3][j] = v.w;
        }
        __syncthreads();
#pragma unroll 16
        for (int kk = 0; kk < 64; ++kk) {
            float xv = Xs[kk][mm];
#pragma unroll
            for (int jj = 0; jj < 8; jj++) acc[jj] += xv * Wsh[kk][j0 + jj];
        }
        __syncthreads();
    }

#pragma unroll
    for (int jj = 0; jj < 8; jj++) Hs[mm][j0 + jj] = acc[jj];
    __syncthreads();

    if (tid < 64) {
        const int n = m0 + tid;
        float h[H4E];
        float mu = 0.f;
#pragma unroll
        for (int j = 0; j < H4E; j++) { h[j] = Hs[tid][j] + gb1[j]; mu += h[j]; }
        mu *= (1.0f / H4E);
        float var = 0.f;
#pragma unroll
        for (int j = 0; j < H4E; j++) { float d = h[j] - mu; var += d * d; }
        var *= (1.0f / H4E);
        const float inv = rsqrtf(var + LN_EPS);
#pragma unroll
        for (int j = 0; j < H4E; j++) {
            float v = (h[j] - mu) * inv * gamma[j] + beta[j];
            h[j] = fmaxf(v, 0.f);
        }
        float best = -3.4e38f, second = -3.4e38f;
        int be = 0, se = 0;
#pragma unroll
        for (int e = 0; e < NE; e++) {
            float g = gb2[e];
#pragma unroll
            for (int j = 0; j < H4E; j++) g += h[j] * gw2[e * H4E + j];
            if (g > best)        { second = best; se = be; best = g; be = e; }
            else if (g > second) { second = g; se = e; }
        }
        const float e1 = __expf(second - best);
        const float s  = 1.f + e1;
        g_topi[n * 2 + 0] = be;
        g_topi[n * 2 + 1] = se;
        g_topg[n * 2 + 0] = 1.f / s;
        g_topg[n * 2 + 1] = e1 / s;
        atomicAdd(&g_counts[be], 1);
        atomicAdd(&g_counts[8 + se], 1);
    }
}

// ---------------------------------------------------------------------------
// Kernel: route tokens into per-expert lists (capacity-filtered, ALPHA folded)
// ---------------------------------------------------------------------------
__global__ __launch_bounds__(256) void route_kernel()
{
    int n = blockIdx.x * 256 + threadIdx.x;
    if (n >= NTOK) return;
#pragma unroll
    for (int k = 0; k < 2; k++) {
        int e   = g_topi[n * 2 + k];
        float w = g_topg[n * 2 + k];
        if (g_counts[k * 8 + e] > CAPACITY) w = 0.f;
        if (w != 0.f) {
            int idx = atomicAdd(&g_ecount[e], 1);
            g_elist[e * 16384 + idx] = n;
            g_ew[e * 16384 + idx]    = w * ALPHA_;
        }
    }
}

// ---------------------------------------------------------------------------
// Kernel: expert-gathered coeff -> fp16 into g_C2 columns
// ---------------------------------------------------------------------------
__global__ __launch_bounds__(128) void coeff2_kernel(
    const float* __restrict__ x, const float* __restrict__ lA)
{
    __shared__ float Xs[128][33];
    __shared__ float As[32][16];
    __shared__ int   Ts[128];
    __shared__ float Wsc[128];

    const int e    = blockIdx.x;
    const int base = blockIdx.y * 128;
    const int cnt  = g_ecount[e];
    if (base >= cnt) return;
    const int tid = threadIdx.x;
    const int T   = min(128, cnt - base);

    {
        int i = min(tid, T - 1);
        Ts[tid]  = g_elist[e * 16384 + base + i];
        Wsc[tid] = g_ew[e * 16384 + base + i];
    }
    __syncthreads();

    float acc[16];
#pragma unroll
    for (int r = 0; r < 16; r++) acc[r] = 0.f;

    const float* Ae = lA + (size_t)e * INDIM * RR;

    for (int k0 = 0; k0 < INDIM; k0 += 32) {
#pragma unroll
        for (int i = 0; i < 8; i++) {
            int s   = tid + i * 128;
            int row = s >> 3;
            int f4  = (s & 7) << 2;
            float4 v = *(const float4*)(x + (size_t)Ts[row] * INDIM + k0 + f4);
            Xs[row][f4 + 0] = v.x; Xs[row][f4 + 1] = v.y;
            Xs[row][f4 + 2] = v.z; Xs[row][f4 + 3] = v.w;
        }
#pragma unroll
        for (int i = 0; i < 4; i++) {
            int s  = tid + i * 128;
            int kk = s >> 4;
            int r  = s & 15;
            As[kk][r] = Ae[(size_t)(k0 + kk) * RR + r];
        }
        __syncthreads();
#pragma unroll 8
        for (int kk = 0; kk < 32; kk++) {
            float xv = Xs[tid][kk];
            float4 a0 = *(const float4*)&As[kk][0];
            float4 a1 = *(const float4*)&As[kk][4];
            float4 a2 = *(const float4*)&As[kk][8];
            float4 a3 = *(const float4*)&As[kk][12];
            acc[0]  += xv * a0.x; acc[1]  += xv * a0.y; acc[2]  += xv * a0.z; acc[3]  += xv * a0.w;
            acc[4]  += xv * a1.x; acc[5]  += xv * a1.y; acc[6]  += xv * a1.z; acc[7]  += xv * a1.w;
            acc[8]  += xv * a2.x; acc[9]  += xv * a2.y; acc[10] += xv * a2.z; acc[11] += xv * a2.w;
            acc[12] += xv * a3.x; acc[13] += xv * a3.y; acc[14] += xv * a3.z; acc[15] += xv * a3.w;
        }
        __syncthreads();
    }

    if (tid < T) {
        float w = Wsc[tid];
        __half* dst = g_C2 + (size_t)Ts[tid] * 128 + e * RR;
#pragma unroll
        for (int r = 0; r < 16; r++) dst[r] = __float2half_rn(w * acc[r]);
    }
}

// ---------------------------------------------------------------------------
// Kernel: fp16 mma.sync GEMM, augmented K = 4224, register-staged loads.
// BM=BN=128, 256 threads (8 warps 4x2), warp tile 32x64, 2 smem buffers
// (fp16 only, 40 KB), LDG.128 fp32 -> reg convert -> STS fp16.
// One __syncthreads per k-tile; 2 CTAs/SM.
// ---------------------------------------------------------------------------
__global__ __launch_bounds__(256, 2) void gemm_kernel(
    const float* __restrict__ x, const float* __restrict__ W,
    float* __restrict__ out)
{
    __shared__ __half smem[2][STAGEH];

    const int tid  = threadIdx.x;
    const int lane = tid & 31;
    const int warp = tid >> 5;
    const int wm   = warp & 3;
    const int wn   = warp >> 2;

    // panel swizzle: 4 panels of 16 m-blocks x 32 n-blocks
    const int b     = blockIdx.x;
    const int panel = b >> 9;
    const int r     = b & 511;
    const int m0    = (panel * 16 + (r & 15)) * 128;
    const int n0    = (r >> 4) * 128;

    float acc[2][8][4];
#pragma unroll
    for (int i = 0; i < 2; i++)
#pragma unroll
        for (int j = 0; j < 8; j++)
#pragma unroll
            for (int q = 0; q < 4; q++) acc[i][j][q] = 0.f;

    // unified staging registers: main kt -> packed half2 pairs, lora kt -> raw uint4
    uint4 rs[4];

    auto ldg_stage = [&](int kt) {
        if (kt < LORA_KT) {
            const int jb = kt * 32;
#pragma unroll
            for (int i = 0; i < 2; i++) {
                int s2  = tid + i * 256;
                int row = s2 >> 2;
                int c   = (s2 & 3) * 8;
                rs[i]     = *(const uint4*)(g_C2  + (size_t)(m0 + row) * 128 + jb + c);
                rs[2 + i] = *(const uint4*)(g_LBT + (size_t)(n0 + row) * 128 + jb + c);
            }
        } else {
            const int k0 = (kt - LORA_KT) * 32;
#pragma unroll
            for (int i = 0; i < 4; i++) {
                int s2  = tid + i * 256;
                int row = s2 >> 3;
                int c   = (s2 & 7) * 4;
                float4 va = *(const float4*)(x + (size_t)(m0 + row) * INDIM + k0 + c);
                float4 vb = *(const float4*)(W + (size_t)(n0 + row) * INDIM + k0 + c);
                rs[i].x = packh2(va.x, va.y);
                rs[i].y = packh2(va.z, va.w);
                rs[i].z = packh2(vb.x, vb.y);
                rs[i].w = packh2(vb.z, vb.w);
            }
        }
    };

    auto sts_stage = [&](int kt, int buf) {
        __half* As = smem[buf];
        __half* Bs = As + 128 * LDT;
        if (kt < LORA_KT) {
#pragma unroll
            for (int i = 0; i < 2; i++) {
                int s2  = tid + i * 256;
                int row = s2 >> 2;
                int c   = (s2 & 3) * 8;
                *(uint4*)(As + row * LDT + c) = rs[i];
                *(uint4*)(Bs + row * LDT + c) = rs[2 + i];
            }
        } else {
#pragma unroll
            for (int i = 0; i < 4; i++) {
                int s2  = tid + i * 256;
                int row = s2 >> 3;
                int c   = (s2 & 7) * 4;
                *(uint2*)(As + row * LDT + c) = make_uint2(rs[i].x, rs[i].y);
                *(uint2*)(Bs + row * LDT + c) = make_uint2(rs[i].z, rs[i].w);
            }
        }
    };

    ldg_stage(0);
    sts_stage(0, 0);

    for (int kt = 0; kt < KT; kt++) {
        __syncthreads();            // STS(kt) visible; compute(kt-1) readers done
        if (kt + 1 < KT) ldg_stage(kt + 1);

        const uint32_t ab = smem_u32(smem[kt & 1]);
        const uint32_t bb = ab + 128 * LDT * 2;
#pragma unroll
        for (int step = 0; step < 2; step++) {
            const uint32_t abase = ab +
                ((wm * 32 + (lane & 15)) * LDT + step * 16 + (lane >> 4) * 8) * 2;
            const uint32_t bbase = bb +
                ((wn * 64 + (lane & 15)) * LDT + step * 16 + (lane >> 4) * 8) * 2;
            uint32_t A[2][4];
            uint32_t Bf[8][2];
#pragma unroll
            for (int i = 0; i < 2; i++)
                ldsm4(A[i][0], A[i][1], A[i][2], A[i][3], abase + i * 16 * LDT * 2);
#pragma unroll
            for (int j = 0; j < 4; j++) {
                uint32_t r0, r1, r2, r3;
                ldsm4(r0, r1, r2, r3, bbase + j * 16 * LDT * 2);
                Bf[2 * j][0] = r0; Bf[2 * j][1] = r2;
                Bf[2 * j + 1][0] = r1; Bf[2 * j + 1][1] = r3;
            }
#pragma unroll
            for (int i = 0; i < 2; i++)
#pragma unroll
                for (int j = 0; j < 8; j++)
                    mma16816(acc[i][j], A[i], Bf[j]);
        }

        if (kt + 1 < KT) sts_stage(kt + 1, (kt + 1) & 1);
    }

    // epilogue
#pragma unroll
    for (int i = 0; i < 2; i++) {
        const int mrow = m0 + wm * 32 + i * 16 + (lane >> 2);
#pragma unroll
        for (int j = 0; j < 8; j++) {
            const int col = n0 + wn * 64 + j * 8 + (lane & 3) * 2;
            float2 v0 = make_float2(acc[i][j][0], acc[i][j][1]);
            float2 v1 = make_float2(acc[i][j][2], acc[i][j][3]);
            *(float2*)(out + (size_t)mrow * OUTDIM + col)       = v0;
            *(float2*)(out + (size_t)(mrow + 8) * OUTDIM + col) = v1;
        }
    }
}

// ---------------------------------------------------------------------------
// Host entry
// ---------------------------------------------------------------------------
extern "C" void kernel_launch(void* const* d_in, const int* in_sizes, int n_in,
                              void* d_out, int out_size)
{
    const float* x   = (const float*)d_in[0];
    const float* W   = (const float*)d_in[1];
    const float* lA  = (const float*)d_in[2];
    const float* lB  = (const float*)d_in[3];
    const float* gw1 = (const float*)d_in[4];
    const float* gb1 = (const float*)d_in[5];
    const float* gam = (const float*)d_in[6];
    const float* bet = (const float*)d_in[7];
    const float* gw2 = (const float*)d_in[8];
    const float* gb2 = (const float*)d_in[9];
    float* out = (float*)d_out;

    void* p_c2 = nullptr;
    cudaGetSymbolAddress(&p_c2, g_C2);

    zero_kernel<<<1, 32>>>();
    cudaMemsetAsync(p_c2, 0, (size_t)NTOK * 128 * sizeof(__half), 0);
    lbt_kernel<<<dim3(OUTDIM / 256, 128), 256>>>(lB);

    gate_kernel<<<NTOK / 64, 256>>>(x, gw1, gb1, gam, bet, gw2, gb2);
    route_kernel<<<NTOK / 256, 256>>>();
    coeff2_kernel<<<dim3(NE, 128), 128>>>(x, lA);

    gemm_kernel<<<2048, 256>>>(x, W, out);
}